// round 14
// baseline (speedup 1.0000x reference)
#include <cuda_runtime.h>
#include <cuda_fp16.h>
#include <cstdint>

#define BATCH 4
#define SEQ   2048
#define CDIM  1024
#define NH    16
#define HD    64
#define MTOT  (BATCH*SEQ)   // 8192
#define N3    (3*CDIM)      // 3072

// ---------------- scratch (device globals; no allocation) ----------------
__device__ __half g_xh[MTOT*CDIM];                     // x (fp16)
__device__ __half g_wh[N3*CDIM];                       // qkv_w (fp16)
__device__ __half g_fh[CDIM*CDIM];                     // fc_w (fp16)
__device__ __half g_qb[BATCH*NH*SEQ*HD];               // Q (pre-scaled by 0.125)
__device__ __half g_kb[BATCH*NH*SEQ*HD];               // K
__device__ __half g_vb[BATCH*NH*SEQ*HD];               // V [bh][t][d]
__device__ __half g_ao[MTOT*CDIM];                     // attn out (fp16)

// ---------------- helpers ----------------
__device__ __forceinline__ uint32_t smem_u32(const void* p) {
    uint32_t a;
    asm("{ .reg .u64 t; cvta.to.shared.u64 t, %1; cvt.u32.u64 %0, t; }" : "=r"(a) : "l"(p));
    return a;
}
__device__ __forceinline__ void cp_async16(uint32_t s, const void* g) {
    asm volatile("cp.async.cg.shared.global [%0], [%1], 16;" :: "r"(s), "l"(g));
}
#define CP_COMMIT() asm volatile("cp.async.commit_group;" ::: "memory")
template<int N> __device__ __forceinline__ void cp_wait() {
    asm volatile("cp.async.wait_group %0;" :: "n"(N) : "memory");
}
__device__ __forceinline__ void ldsm_x4(uint32_t* r, uint32_t addr) {
    asm volatile("ldmatrix.sync.aligned.m8n8.x4.shared.b16 {%0,%1,%2,%3}, [%4];"
        : "=r"(r[0]), "=r"(r[1]), "=r"(r[2]), "=r"(r[3]) : "r"(addr));
}
__device__ __forceinline__ void ldsm_x4_t(uint32_t* r, uint32_t addr) {
    asm volatile("ldmatrix.sync.aligned.m8n8.x4.trans.shared.b16 {%0,%1,%2,%3}, [%4];"
        : "=r"(r[0]), "=r"(r[1]), "=r"(r[2]), "=r"(r[3]) : "r"(addr));
}
__device__ __forceinline__ void mma16816(float* c, const uint32_t* a, uint32_t b0, uint32_t b1) {
    asm volatile("mma.sync.aligned.m16n8k16.row.col.f32.f16.f16.f32 "
        "{%0,%1,%2,%3}, {%4,%5,%6,%7}, {%8,%9}, {%0,%1,%2,%3};"
        : "+f"(c[0]), "+f"(c[1]), "+f"(c[2]), "+f"(c[3])
        : "r"(a[0]), "r"(a[1]), "r"(a[2]), "r"(a[3]), "r"(b0), "r"(b1));
}
__device__ __forceinline__ uint32_t h2pack(float a, float b) {
    __half2 p = __floats2half2_rn(a, b);
    return *(uint32_t*)&p;
}

// ---------------- fp32 -> fp16 conversion (single fused launch) ----------------
#define CVT_NX (MTOT * CDIM / 4)
#define CVT_NW (N3 * CDIM / 4)
#define CVT_NF (CDIM * CDIM / 4)
__global__ __launch_bounds__(256) void cvt_all_kernel(const float* __restrict__ x,
                                                      const float* __restrict__ w,
                                                      const float* __restrict__ f) {
    int i = blockIdx.x * blockDim.x + threadIdx.x;
    const float4* src;
    uint2* dst;
    int j;
    if (i < CVT_NX)                { src = (const float4*)x; dst = (uint2*)g_xh; j = i; }
    else if (i < CVT_NX + CVT_NW)  { src = (const float4*)w; dst = (uint2*)g_wh; j = i - CVT_NX; }
    else                           { src = (const float4*)f; dst = (uint2*)g_fh; j = i - CVT_NX - CVT_NW; }
    float4 v = src[j];
    dst[j] = make_uint2(h2pack(v.x, v.y), h2pack(v.z, v.w));
}

// ---------------------------------------------------------------------------
// GEMM (raw mma): block 128x256, 8 warps (2x4), warp tile 64x64, K-chunk 64,
// cp.async 3-stage single-barrier.
// smem stage: A[128][72]h (18432 B) | B[256][72]h (36864 B) = 55296 B; 3 stages.
// ---------------------------------------------------------------------------
#define G_LD     72
#define G_ABYTES (128 * G_LD * 2)       // 18432
#define G_BBYTES (256 * G_LD * 2)       // 36864
#define G_STAGE  (G_ABYTES + G_BBYTES)  // 55296
#define G_SMEM   (3 * G_STAGE)          // 165888
#define G_NCH    (CDIM / 64)            // 16

// chunk ch -> stage st. 256 threads. A: 128 rows, B: 256 rows; q = 16B col idx.
#define GEMM_ISSUE(Ag, Bg, ch, st) do { \
    _Pragma("unroll") \
    for (int r_ = 0; r_ < 4; r_++) { \
        int u_ = tid + r_ * 256; \
        int row_ = u_ >> 3, q_ = u_ & 7; \
        uint32_t so_ = sbase + (st) * G_STAGE + (uint32_t)(row_ * G_LD + q_ * 8) * 2; \
        cp_async16(so_, &(Ag)[(long)(bm + row_) * CDIM + (ch) * 64 + q_ * 8]); \
    } \
    _Pragma("unroll") \
    for (int r_ = 0; r_ < 8; r_++) { \
        int u_ = tid + r_ * 256; \
        int row_ = u_ >> 3, q_ = u_ & 7; \
        uint32_t so_ = sbase + (st) * G_STAGE + G_ABYTES + (uint32_t)(row_ * G_LD + q_ * 8) * 2; \
        cp_async16(so_, &(Bg)[(long)(bn + row_) * CDIM + (ch) * 64 + q_ * 8]); \
    } \
    CP_COMMIT(); \
} while (0)

// compute one K=64 chunk from stage st into acc[4][8][4] (warp tile 64x64)
#define GEMM_COMPUTE(st) do { \
    uint32_t Ast_ = sbase + (st) * G_STAGE; \
    uint32_t Bst_ = Ast_ + G_ABYTES; \
    _Pragma("unroll") \
    for (int kb_ = 0; kb_ < 2; kb_++) { \
        uint32_t bb_[8][4]; \
        _Pragma("unroll") \
        for (int ng_ = 0; ng_ < 8; ng_++) \
            ldsm_x4(bb_[ng_], Bst_ + (uint32_t)((wn * 64 + ng_ * 8 + (lane & 7)) * G_LD \
                                                + kb_ * 32 + (lane >> 3) * 8) * 2); \
        _Pragma("unroll") \
        for (int ks_ = 0; ks_ < 2; ks_++) { \
            uint32_t a_[4][4]; \
            _Pragma("unroll") \
            for (int mi_ = 0; mi_ < 4; mi_++) \
                ldsm_x4(a_[mi_], Ast_ + (uint32_t)((wm * 64 + mi_ * 16 + (lane & 15)) * G_LD \
                                                   + kb_ * 32 + ks_ * 16 + (lane >> 4) * 8) * 2); \
            _Pragma("unroll") \
            for (int mi_ = 0; mi_ < 4; mi_++) \
                _Pragma("unroll") \
                for (int ng_ = 0; ng_ < 8; ng_++) \
                    mma16816(acc[mi_][ng_], a_[mi_], bb_[ng_][ks_ * 2], bb_[ng_][ks_ * 2 + 1]); \
        } \
    } \
} while (0)

#define GEMM_MAINLOOP(Ag, Bg) do { \
    GEMM_ISSUE(Ag, Bg, 0, 0); \
    GEMM_ISSUE(Ag, Bg, 1, 1); \
    for (int ch = 0; ch < G_NCH; ch++) { \
        int st = ch % 3; \
        if (ch + 2 < G_NCH) cp_wait<1>(); else cp_wait<0>(); \
        __syncthreads(); \
        if (ch + 2 < G_NCH) GEMM_ISSUE(Ag, Bg, ch + 2, (ch + 2) % 3); \
        GEMM_COMPUTE(st); \
    } \
} while (0)

// ---------------- GEMM1: qkv = x @ qkv_w^T + b ; scatter q/k/v fp16 ----------------
__global__ __launch_bounds__(256, 1) void gemm_qkv_mma(const float* __restrict__ bias) {
    extern __shared__ char smraw[];
    uint32_t sbase = smem_u32(smraw);
    int tid = threadIdx.x, warp = tid >> 5, lane = tid & 31;
    int wm = warp >> 2, wn = warp & 3;
    int bm = blockIdx.y * 128, bn = blockIdx.x * 256;

    float acc[4][8][4];
    #pragma unroll
    for (int i = 0; i < 4; i++)
        #pragma unroll
        for (int j = 0; j < 8; j++)
            #pragma unroll
            for (int c = 0; c < 4; c++) acc[i][j][c] = 0.f;

    GEMM_MAINLOOP(g_xh, g_wh);

    // epilogue: register -> GMEM scatter (no smem staging)
    int b = bm >> 11;
    int colp = (lane & 3) * 2;
    float bias0[8], bias1[8], scale[8];
    __half* base[8];
    #pragma unroll
    for (int ng = 0; ng < 8; ng++) {
        int n0 = bn + wn * 64 + ng * 8 + colp;
        bias0[ng] = __ldg(&bias[n0]);
        bias1[ng] = __ldg(&bias[n0 + 1]);
        int which = n0 >> 10;
        int rem = n0 & 1023;
        int h = rem >> 6, d0 = rem & 63;
        scale[ng] = (which == 0) ? 0.125f : 1.0f;
        base[ng] = (which == 0 ? g_qb : which == 1 ? g_kb : g_vb)
                 + ((long)(b * NH + h) * SEQ) * HD + d0;
    }
    #pragma unroll
    for (int mi = 0; mi < 4; mi++) {
        int m0 = bm + wm * 64 + mi * 16 + (lane >> 2);
        #pragma unroll
        for (int rr = 0; rr < 2; rr++) {
            int t = (m0 + rr * 8) & (SEQ - 1);
            #pragma unroll
            for (int ng = 0; ng < 8; ng++) {
                float v0 = (acc[mi][ng][rr * 2]     + bias0[ng]) * scale[ng];
                float v1 = (acc[mi][ng][rr * 2 + 1] + bias1[ng]) * scale[ng];
                *(uint32_t*)(base[ng] + (long)t * HD) = h2pack(v0, v1);
            }
        }
    }
}

// ---------------- GEMM2: out = ao @ fc_w^T + b (fp32 out) ----------------
__global__ __launch_bounds__(256, 1) void gemm_out_mma(const float* __restrict__ bias,
                                                       float* __restrict__ out) {
    extern __shared__ char smraw[];
    uint32_t sbase = smem_u32(smraw);
    int tid = threadIdx.x, warp = tid >> 5, lane = tid & 31;
    int wm = warp >> 2, wn = warp & 3;
    int bm = blockIdx.y * 128, bn = blockIdx.x * 256;

    float acc[4][8][4];
    #pragma unroll
    for (int i = 0; i < 4; i++)
        #pragma unroll
        for (int j = 0; j < 8; j++)
            #pragma unroll
            for (int c = 0; c < 4; c++) acc[i][j][c] = 0.f;

    GEMM_MAINLOOP(g_ao, g_fh);

    int colp = (lane & 3) * 2;
    float bias0[8], bias1[8];
    int ncol[8];
    #pragma unroll
    for (int ng = 0; ng < 8; ng++) {
        int n0 = bn + wn * 64 + ng * 8 + colp;
        ncol[ng] = n0;
        bias0[ng] = __ldg(&bias[n0]);
        bias1[ng] = __ldg(&bias[n0 + 1]);
    }
    #pragma unroll
    for (int mi = 0; mi < 4; mi++) {
        int m0 = bm + wm * 64 + mi * 16 + (lane >> 2);
        #pragma unroll
        for (int rr = 0; rr < 2; rr++) {
            long mrow = (long)(m0 + rr * 8) * CDIM;
            #pragma unroll
            for (int ng = 0; ng < 8; ng++) {
                float2 v;
                v.x = acc[mi][ng][rr * 2]     + bias0[ng];
                v.y = acc[mi][ng][rr * 2 + 1] + bias1[ng];
                *(float2*)(out + mrow + ncol[ng]) = v;
            }
        }
    }
}

// ---------------------------------------------------------------------------
// Attention: FA2-style raw mma (unchanged from R12). Block = 128 queries,
// 128 thr (4 warps x 2 m-groups). 64-key tiles, cp.async 2-stage K/V.
// ---------------------------------------------------------------------------
#define AT_LD  72
#define AT_QB  (128 * AT_LD * 2)             // 18432
#define AT_KB  (64 * AT_LD * 2)              // 9216
#define AT_Q   0
#define AT_K   (AT_QB)
#define AT_V   (AT_QB + 2 * AT_KB)
#define AT_SMEM (AT_QB + 4 * AT_KB)          // 55296

__global__ __launch_bounds__(128, 2) void attn_mma() {
    extern __shared__ char smraw[];
    uint32_t sbase = smem_u32(smraw);
    __half* Qs = (__half*)(smraw + AT_Q);

    int tid = threadIdx.x, warp = tid >> 5, lane = tid & 31;
    int bh = blockIdx.y;
    int q0 = blockIdx.x * 128;
    long qbase = ((long)bh * SEQ + q0) * HD;

    {
        long kb = (long)bh * SEQ * HD;
        #pragma unroll
        for (int r = 0; r < 4; r++) {
            int u = tid + r * 128;
            int row = u >> 3, q = u & 7;
            uint32_t so = (uint32_t)(row * AT_LD + q * 8) * 2;
            cp_async16(sbase + AT_K + so, &g_kb[kb + (long)row * HD + q * 8]);
            cp_async16(sbase + AT_V + so, &g_vb[kb + (long)row * HD + q * 8]);
        }
        CP_COMMIT();
        #pragma unroll
        for (int r = 0; r < 8; r++) {
            int u = tid + r * 128;
            int row = u >> 3, q = u & 7;
            *(uint4*)&Qs[row * AT_LD + q * 8] =
                *(const uint4*)&g_qb[qbase + (long)row * HD + q * 8];
        }
    }
    __syncthreads();

    uint32_t qa[2][4][4];
    #pragma unroll
    for (int mg = 0; mg < 2; mg++) {
        uint32_t qrow = warp * 32 + mg * 16 + (lane & 15);
        #pragma unroll
        for (int kk = 0; kk < 4; kk++) {
            uint32_t addr = sbase + AT_Q + (uint32_t)(qrow * AT_LD + kk * 16 + (lane >> 4) * 8) * 2;
            ldsm_x4(qa[mg][kk], addr);
        }
    }

    float oc[2][8][4];
    #pragma unroll
    for (int mg = 0; mg < 2; mg++)
        #pragma unroll
        for (int i = 0; i < 8; i++)
            #pragma unroll
            for (int j = 0; j < 4; j++) oc[mg][i][j] = 0.f;
    float rs[2][2] = {{0.f, 0.f}, {0.f, 0.f}};

    for (int tile = 0; tile < 32; tile++) {
        int st = tile & 1;
        cp_wait<0>();
        __syncthreads();
        if (tile + 1 < 32) {
            long kb = ((long)bh * SEQ + (tile + 1) * 64) * HD;
            uint32_t kdst = sbase + AT_K + (st ^ 1) * AT_KB;
            uint32_t vdst = sbase + AT_V + (st ^ 1) * AT_KB;
            #pragma unroll
            for (int r = 0; r < 4; r++) {
                int u = tid + r * 128;
                int row = u >> 3, q = u & 7;
                uint32_t so = (uint32_t)(row * AT_LD + q * 8) * 2;
                cp_async16(kdst + so, &g_kb[kb + (long)row * HD + q * 8]);
                cp_async16(vdst + so, &g_vb[kb + (long)row * HD + q * 8]);
            }
            CP_COMMIT();
        }

        uint32_t Kst = sbase + AT_K + st * AT_KB;
        uint32_t Vst = sbase + AT_V + st * AT_KB;

        float sc[2][8][4];
        #pragma unroll
        for (int kg = 0; kg < 8; kg++) {
            uint32_t kaddr = Kst + (uint32_t)((kg * 8 + (lane & 7)) * AT_LD + (lane >> 3) * 8) * 2;
            uint32_t kb0[4], kb1[4];
            ldsm_x4(kb0, kaddr);
            ldsm_x4(kb1, kaddr + 64);
            #pragma unroll
            for (int mg = 0; mg < 2; mg++) {
                #pragma unroll
                for (int j = 0; j < 4; j++) sc[mg][kg][j] = 0.f;
                mma16816(sc[mg][kg], qa[mg][0], kb0[0], kb0[1]);
                mma16816(sc[mg][kg], qa[mg][1], kb0[2], kb0[3]);
                mma16816(sc[mg][kg], qa[mg][2], kb1[0], kb1[1]);
                mma16816(sc[mg][kg], qa[mg][3], kb1[2], kb1[3]);
            }
        }

        uint32_t pa[2][4][4];
        #pragma unroll
        for (int mg = 0; mg < 2; mg++) {
            #pragma unroll
            for (int kp = 0; kp < 4; kp++) {
                float e0 = __expf(sc[mg][2*kp][0]),   e1 = __expf(sc[mg][2*kp][1]);
                float e2 = __expf(sc[mg][2*kp][2]),   e3 = __expf(sc[mg][2*kp][3]);
                float f0 = __expf(sc[mg][2*kp+1][0]), f1 = __expf(sc[mg][2*kp+1][1]);
                float f2 = __expf(sc[mg][2*kp+1][2]), f3 = __expf(sc[mg][2*kp+1][3]);
                rs[mg][0] += (e0 + e1) + (f0 + f1);
                rs[mg][1] += (e2 + e3) + (f2 + f3);
                pa[mg][kp][0] = h2pack(e0, e1);
                pa[mg][kp][1] = h2pack(e2, e3);
                pa[mg][kp][2] = h2pack(f0, f1);
                pa[mg][kp][3] = h2pack(f2, f3);
            }
        }

        #pragma unroll
        for (int kp = 0; kp < 4; kp++) {
            #pragma unroll
            for (int np = 0; np < 4; np++) {
                uint32_t vaddr = Vst + (uint32_t)((kp * 16 + (lane & 15)) * AT_LD
                                                  + np * 16 + (lane >> 4) * 8) * 2;
                uint32_t vb[4];
                ldsm_x4_t(vb, vaddr);
                #pragma unroll
                for (int mg = 0; mg < 2; mg++) {
                    mma16816(oc[mg][np * 2],     pa[mg][kp], vb[0], vb[1]);
                    mma16816(oc[mg][np * 2 + 1], pa[mg][kp], vb[2], vb[3]);
                }
            }
        }
    }

    #pragma unroll
    for (int mg = 0; mg < 2; mg++) {
        rs[mg][0] += __shfl_xor_sync(0xffffffffu, rs[mg][0], 1);
        rs[mg][0] += __shfl_xor_sync(0xffffffffu, rs[mg][0], 2);
        rs[mg][1] += __shfl_xor_sync(0xffffffffu, rs[mg][1], 1);
        rs[mg][1] += __shfl_xor_sync(0xffffffffu, rs[mg][1], 2);
    }

    int b = bh >> 4, h = bh & 15;
    #pragma unroll
    for (int mg = 0; mg < 2; mg++) {
        float inv0 = 1.f / rs[mg][0], inv1 = 1.f / rs[mg][1];
        int r0 = q0 + warp * 32 + mg * 16 + (lane >> 2);
        long ob0 = (long)(b * SEQ + r0) * CDIM + h * HD;
        long ob1 = ob0 + 8L * CDIM;
        #pragma unroll
        for (int dg = 0; dg < 8; dg++) {
            int col = dg * 8 + (lane & 3) * 2;
            *(uint32_t*)&g_ao[ob0 + col] = h2pack(oc[mg][dg][0] * inv0, oc[mg][dg][1] * inv0);
            *(uint32_t*)&g_ao[ob1 + col] = h2pack(oc[mg][dg][2] * inv1, oc[mg][dg][3] * inv1);
        }
    }
}

// ---------------------------------------------------------------------------
extern "C" void kernel_launch(void* const* d_in, const int* in_sizes, int n_in,
                              void* d_out, int out_size) {
    const float* x     = (const float*)d_in[0];
    const float* qkv_w = (const float*)d_in[1];
    const float* qkv_b = (const float*)d_in[2];
    const float* fc_w  = (const float*)d_in[3];
    const float* fc_b  = (const float*)d_in[4];
    float* out = (float*)d_out;

    static bool attr_done = false;
    if (!attr_done) {
        cudaFuncSetAttribute(gemm_qkv_mma, cudaFuncAttributeMaxDynamicSharedMemorySize, G_SMEM);
        cudaFuncSetAttribute(gemm_out_mma, cudaFuncAttributeMaxDynamicSharedMemorySize, G_SMEM);
        cudaFuncSetAttribute(attn_mma,     cudaFuncAttributeMaxDynamicSharedMemorySize, AT_SMEM);
        attr_done = true;
    }

    cvt_all_kernel<<<(CVT_NX + CVT_NW + CVT_NF) / 256, 256>>>(x, qkv_w, fc_w);

    dim3 g1(N3 / 256, MTOT / 128);     // 12 x 64
    gemm_qkv_mma<<<g1, 256, G_SMEM>>>(qkv_b);

    dim3 ga(SEQ / 128, BATCH * NH);    // 16 x 64
    attn_mma<<<ga, 128, AT_SMEM>>>();

    dim3 g2(CDIM / 256, MTOT / 128);   // 4 x 64
    gemm_out_mma<<<g2, 256, G_SMEM>>>(fc_b, out);
}

// round 15
// speedup vs baseline: 1.2481x; 1.2481x over previous
#include <cuda_runtime.h>
#include <cuda.h>
#include <cuda_fp16.h>
#include <cstdint>

#define BATCH 4
#define SEQ   2048
#define CDIM  1024
#define NH    16
#define HD    64
#define MTOT  (BATCH*SEQ)   // 8192
#define N3    (3*CDIM)      // 3072

// ---------------- scratch (device globals; no allocation) ----------------
__device__ __half g_xh[MTOT*CDIM];                     // x (fp16)
__device__ __half g_wh[N3*CDIM];                       // qkv_w (fp16)
__device__ __half g_fh[CDIM*CDIM];                     // fc_w (fp16)
__device__ __half g_qb[BATCH*NH*SEQ*HD];               // Q (pre-scaled by 0.125)
__device__ __half g_kb[BATCH*NH*SEQ*HD];               // K
__device__ __half g_vb[BATCH*NH*SEQ*HD];               // V [bh][t][d]
__device__ __half g_ao[MTOT*CDIM];                     // attn out (fp16)

// ---------------- helpers ----------------
__device__ __forceinline__ uint32_t smem_u32(const void* p) {
    uint32_t a;
    asm("{ .reg .u64 t; cvta.to.shared.u64 t, %1; cvt.u32.u64 %0, t; }" : "=r"(a) : "l"(p));
    return a;
}
__device__ __forceinline__ void cp_async16(uint32_t s, const void* g) {
    asm volatile("cp.async.cg.shared.global [%0], [%1], 16;" :: "r"(s), "l"(g));
}
#define CP_COMMIT() asm volatile("cp.async.commit_group;" ::: "memory")
template<int N> __device__ __forceinline__ void cp_wait() {
    asm volatile("cp.async.wait_group %0;" :: "n"(N) : "memory");
}
__device__ __forceinline__ void ldsm_x4(uint32_t* r, uint32_t addr) {
    asm volatile("ldmatrix.sync.aligned.m8n8.x4.shared.b16 {%0,%1,%2,%3}, [%4];"
        : "=r"(r[0]), "=r"(r[1]), "=r"(r[2]), "=r"(r[3]) : "r"(addr));
}
__device__ __forceinline__ void ldsm_x4_t(uint32_t* r, uint32_t addr) {
    asm volatile("ldmatrix.sync.aligned.m8n8.x4.trans.shared.b16 {%0,%1,%2,%3}, [%4];"
        : "=r"(r[0]), "=r"(r[1]), "=r"(r[2]), "=r"(r[3]) : "r"(addr));
}
__device__ __forceinline__ void mma16816(float* c, const uint32_t* a, uint32_t b0, uint32_t b1) {
    asm volatile("mma.sync.aligned.m16n8k16.row.col.f32.f16.f16.f32 "
        "{%0,%1,%2,%3}, {%4,%5,%6,%7}, {%8,%9}, {%0,%1,%2,%3};"
        : "+f"(c[0]), "+f"(c[1]), "+f"(c[2]), "+f"(c[3])
        : "r"(a[0]), "r"(a[1]), "r"(a[2]), "r"(a[3]), "r"(b0), "r"(b1));
}
__device__ __forceinline__ uint32_t h2pack(float a, float b) {
    __half2 p = __floats2half2_rn(a, b);
    return *(uint32_t*)&p;
}
// mbarrier
#define MBARRIER_INIT(mb, c) \
    asm volatile("mbarrier.init.shared.b64 [%0], %1;" :: "r"((uint32_t)(mb)), "r"((uint32_t)(c)) : "memory")
#define MBARRIER_EXPECT_TX(mb, tx) \
    asm volatile("mbarrier.arrive.expect_tx.shared.b64 _, [%0], %1;" \
                 :: "r"((uint32_t)(mb)), "r"((uint32_t)(tx)) : "memory")
#define MBARRIER_WAIT_PARITY(mb, ph) do { \
    uint32_t _m = (uint32_t)(mb), _p = (uint32_t)(ph), _d; \
    asm volatile("{\n\t.reg .pred p;\n\t" \
        "mbarrier.try_wait.parity.acquire.cta.shared::cta.b64 p, [%1], %2;\n\t" \
        "selp.b32 %0, 1, 0, p;\n\t}" : "=r"(_d) : "r"(_m), "r"(_p) : "memory"); \
    if (!_d) { \
        asm volatile("{\n\t.reg .pred P1;\n\t" \
            "WL_%=:\n\t" \
            "mbarrier.try_wait.parity.acquire.cta.shared::cta.b64 P1, [%0], %1, 0x989680;\n\t" \
            "@P1 bra.uni WD_%=;\n\tbra.uni WL_%=;\n\tWD_%=:\n\t}" \
            :: "r"(_m), "r"(_p) : "memory"); \
    } \
} while(0)
// 2D TMA load: global -> shared::cta, mbarrier complete_tx
__device__ __forceinline__ void tma2d(uint32_t dst, const CUtensorMap* m,
                                      int x, int y, uint32_t mbar) {
    asm volatile(
        "cp.async.bulk.tensor.2d.shared::cta.global.tile.mbarrier::complete_tx::bytes "
        "[%0], [%1, {%2, %3}], [%4];"
        :: "r"(dst), "l"(m), "r"(x), "r"(y), "r"(mbar) : "memory");
}
#define GSWZ(o) ((o) ^ (((o) >> 3) & 0x70))

// ---------------- fp32 -> fp16 conversion (single fused launch) ----------------
#define CVT_NX (MTOT * CDIM / 4)
#define CVT_NW (N3 * CDIM / 4)
#define CVT_NF (CDIM * CDIM / 4)
__global__ __launch_bounds__(256) void cvt_all_kernel(const float* __restrict__ x,
                                                      const float* __restrict__ w,
                                                      const float* __restrict__ f) {
    int i = blockIdx.x * blockDim.x + threadIdx.x;
    const float4* src;
    uint2* dst;
    int j;
    if (i < CVT_NX)                { src = (const float4*)x; dst = (uint2*)g_xh; j = i; }
    else if (i < CVT_NX + CVT_NW)  { src = (const float4*)w; dst = (uint2*)g_wh; j = i - CVT_NX; }
    else                           { src = (const float4*)f; dst = (uint2*)g_fh; j = i - CVT_NX - CVT_NW; }
    float4 v = src[j];
    dst[j] = make_uint2(h2pack(v.x, v.y), h2pack(v.z, v.w));
}

// ---------------------------------------------------------------------------
// GEMM (TMA + raw mma): block 128x128, 4 warps (2x2), warp tile 64x64,
// K-chunk 64, 3-stage, single barrier per chunk, mbarrier-tracked TMA loads.
// Stage: A[128 rows][128 B] (16384) | B[128 rows][128 B] (16384). SW128 layout.
// ---------------------------------------------------------------------------
#define GT_STAGE 32768
#define GT_MBAR  (3 * GT_STAGE)          // 98304
#define GT_SMEM  (GT_MBAR + 128)
#define G_NCH    (CDIM / 64)             // 16

#define GEMM_TMA_ISSUE(ch, st) do { \
    if (tid == 0) { \
        uint32_t mb_ = sbase + GT_MBAR + (st) * 8; \
        MBARRIER_EXPECT_TX(mb_, (uint32_t)GT_STAGE); \
        tma2d(sbase + (st) * GT_STAGE,         &tmA, (ch) * 64, bm, mb_); \
        tma2d(sbase + (st) * GT_STAGE + 16384, &tmB, (ch) * 64, bn, mb_); \
    } \
} while (0)

#define GEMM_COMPUTE(st) do { \
    uint32_t Ast_ = sbase + (st) * GT_STAGE; \
    uint32_t Bst_ = Ast_ + 16384; \
    _Pragma("unroll") \
    for (int kb_ = 0; kb_ < 2; kb_++) { \
        uint32_t bb_[8][4]; \
        _Pragma("unroll") \
        for (int ng_ = 0; ng_ < 8; ng_++) { \
            uint32_t o_ = (uint32_t)((wn * 64 + ng_ * 8 + (lane & 7)) * 128 \
                                     + kb_ * 64 + (lane >> 3) * 16); \
            ldsm_x4(bb_[ng_], Bst_ + GSWZ(o_)); \
        } \
        _Pragma("unroll") \
        for (int ks_ = 0; ks_ < 2; ks_++) { \
            uint32_t a_[4][4]; \
            _Pragma("unroll") \
            for (int mi_ = 0; mi_ < 4; mi_++) { \
                uint32_t o_ = (uint32_t)((wm * 64 + mi_ * 16 + (lane & 15)) * 128 \
                                         + kb_ * 64 + ks_ * 32 + (lane >> 4) * 16); \
                ldsm_x4(a_[mi_], Ast_ + GSWZ(o_)); \
            } \
            _Pragma("unroll") \
            for (int mi_ = 0; mi_ < 4; mi_++) \
                _Pragma("unroll") \
                for (int ng_ = 0; ng_ < 8; ng_++) \
                    mma16816(acc[mi_][ng_], a_[mi_], bb_[ng_][ks_ * 2], bb_[ng_][ks_ * 2 + 1]); \
        } \
    } \
} while (0)

#define GEMM_MAINLOOP() do { \
    if (tid == 0) { \
        MBARRIER_INIT(sbase + GT_MBAR + 0, 1); \
        MBARRIER_INIT(sbase + GT_MBAR + 8, 1); \
        MBARRIER_INIT(sbase + GT_MBAR + 16, 1); \
    } \
    __syncthreads(); \
    GEMM_TMA_ISSUE(0, 0); \
    GEMM_TMA_ISSUE(1, 1); \
    for (int ch = 0; ch < G_NCH; ch++) { \
        int st = ch % 3; \
        MBARRIER_WAIT_PARITY(sbase + GT_MBAR + st * 8, (ch / 3) & 1); \
        __syncthreads(); \
        if (ch + 2 < G_NCH) GEMM_TMA_ISSUE(ch + 2, (ch + 2) % 3); \
        GEMM_COMPUTE(st); \
    } \
} while (0)

// ---------------- GEMM1: qkv = x @ qkv_w^T + b ; scatter q/k/v fp16 ----------------
__global__ __launch_bounds__(128, 2) void gemm_qkv_tma(
    const __grid_constant__ CUtensorMap tmA,
    const __grid_constant__ CUtensorMap tmB,
    const float* __restrict__ bias)
{
    extern __shared__ __align__(128) char smraw[];
    uint32_t sbase = smem_u32(smraw);
    int tid = threadIdx.x, warp = tid >> 5, lane = tid & 31;
    int wm = warp >> 1, wn = warp & 1;
    int bm = blockIdx.y * 128, bn = blockIdx.x * 128;

    float acc[4][8][4];
    #pragma unroll
    for (int i = 0; i < 4; i++)
        #pragma unroll
        for (int j = 0; j < 8; j++)
            #pragma unroll
            for (int c = 0; c < 4; c++) acc[i][j][c] = 0.f;

    GEMM_MAINLOOP();

    // epilogue: register -> GMEM scatter (no smem staging)
    int b = bm >> 11;
    int colp = (lane & 3) * 2;
    float bias0[8], bias1[8], scale[8];
    __half* base[8];
    #pragma unroll
    for (int ng = 0; ng < 8; ng++) {
        int n0 = bn + wn * 64 + ng * 8 + colp;
        bias0[ng] = __ldg(&bias[n0]);
        bias1[ng] = __ldg(&bias[n0 + 1]);
        int which = n0 >> 10;
        int rem = n0 & 1023;
        int h = rem >> 6, d0 = rem & 63;
        scale[ng] = (which == 0) ? 0.125f : 1.0f;
        base[ng] = (which == 0 ? g_qb : which == 1 ? g_kb : g_vb)
                 + ((long)(b * NH + h) * SEQ) * HD + d0;
    }
    #pragma unroll
    for (int mi = 0; mi < 4; mi++) {
        int m0 = bm + wm * 64 + mi * 16 + (lane >> 2);
        #pragma unroll
        for (int rr = 0; rr < 2; rr++) {
            int t = (m0 + rr * 8) & (SEQ - 1);
            #pragma unroll
            for (int ng = 0; ng < 8; ng++) {
                float v0 = (acc[mi][ng][rr * 2]     + bias0[ng]) * scale[ng];
                float v1 = (acc[mi][ng][rr * 2 + 1] + bias1[ng]) * scale[ng];
                *(uint32_t*)(base[ng] + (long)t * HD) = h2pack(v0, v1);
            }
        }
    }
}

// ---------------- GEMM2: out = ao @ fc_w^T + b (fp32 out) ----------------
__global__ __launch_bounds__(128, 2) void gemm_out_tma(
    const __grid_constant__ CUtensorMap tmA,
    const __grid_constant__ CUtensorMap tmB,
    const float* __restrict__ bias, float* __restrict__ out)
{
    extern __shared__ __align__(128) char smraw[];
    uint32_t sbase = smem_u32(smraw);
    int tid = threadIdx.x, warp = tid >> 5, lane = tid & 31;
    int wm = warp >> 1, wn = warp & 1;
    int bm = blockIdx.y * 128, bn = blockIdx.x * 128;

    float acc[4][8][4];
    #pragma unroll
    for (int i = 0; i < 4; i++)
        #pragma unroll
        for (int j = 0; j < 8; j++)
            #pragma unroll
            for (int c = 0; c < 4; c++) acc[i][j][c] = 0.f;

    GEMM_MAINLOOP();

    int colp = (lane & 3) * 2;
    float bias0[8], bias1[8];
    int ncol[8];
    #pragma unroll
    for (int ng = 0; ng < 8; ng++) {
        int n0 = bn + wn * 64 + ng * 8 + colp;
        ncol[ng] = n0;
        bias0[ng] = __ldg(&bias[n0]);
        bias1[ng] = __ldg(&bias[n0 + 1]);
    }
    #pragma unroll
    for (int mi = 0; mi < 4; mi++) {
        int m0 = bm + wm * 64 + mi * 16 + (lane >> 2);
        #pragma unroll
        for (int rr = 0; rr < 2; rr++) {
            long mrow = (long)(m0 + rr * 8) * CDIM;
            #pragma unroll
            for (int ng = 0; ng < 8; ng++) {
                float2 v;
                v.x = acc[mi][ng][rr * 2]     + bias0[ng];
                v.y = acc[mi][ng][rr * 2 + 1] + bias1[ng];
                *(float2*)(out + mrow + ncol[ng]) = v;
            }
        }
    }
}

// ---------------------------------------------------------------------------
// Attention: FA2-style raw mma (unchanged from R12). Block = 128 queries,
// 128 thr (4 warps x 2 m-groups). 64-key tiles, cp.async 2-stage K/V.
// ---------------------------------------------------------------------------
#define AT_LD  72
#define AT_QB  (128 * AT_LD * 2)             // 18432
#define AT_KB  (64 * AT_LD * 2)              // 9216
#define AT_Q   0
#define AT_K   (AT_QB)
#define AT_V   (AT_QB + 2 * AT_KB)
#define AT_SMEM (AT_QB + 4 * AT_KB)          // 55296

__global__ __launch_bounds__(128, 2) void attn_mma() {
    extern __shared__ char smraw[];
    uint32_t sbase = smem_u32(smraw);
    __half* Qs = (__half*)(smraw + AT_Q);

    int tid = threadIdx.x, warp = tid >> 5, lane = tid & 31;
    int bh = blockIdx.y;
    int q0 = blockIdx.x * 128;
    long qbase = ((long)bh * SEQ + q0) * HD;

    {
        long kb = (long)bh * SEQ * HD;
        #pragma unroll
        for (int r = 0; r < 4; r++) {
            int u = tid + r * 128;
            int row = u >> 3, q = u & 7;
            uint32_t so = (uint32_t)(row * AT_LD + q * 8) * 2;
            cp_async16(sbase + AT_K + so, &g_kb[kb + (long)row * HD + q * 8]);
            cp_async16(sbase + AT_V + so, &g_vb[kb + (long)row * HD + q * 8]);
        }
        CP_COMMIT();
        #pragma unroll
        for (int r = 0; r < 8; r++) {
            int u = tid + r * 128;
            int row = u >> 3, q = u & 7;
            *(uint4*)&Qs[row * AT_LD + q * 8] =
                *(const uint4*)&g_qb[qbase + (long)row * HD + q * 8];
        }
    }
    __syncthreads();

    uint32_t qa[2][4][4];
    #pragma unroll
    for (int mg = 0; mg < 2; mg++) {
        uint32_t qrow = warp * 32 + mg * 16 + (lane & 15);
        #pragma unroll
        for (int kk = 0; kk < 4; kk++) {
            uint32_t addr = sbase + AT_Q + (uint32_t)(qrow * AT_LD + kk * 16 + (lane >> 4) * 8) * 2;
            ldsm_x4(qa[mg][kk], addr);
        }
    }

    float oc[2][8][4];
    #pragma unroll
    for (int mg = 0; mg < 2; mg++)
        #pragma unroll
        for (int i = 0; i < 8; i++)
            #pragma unroll
            for (int j = 0; j < 4; j++) oc[mg][i][j] = 0.f;
    float rs[2][2] = {{0.f, 0.f}, {0.f, 0.f}};

    for (int tile = 0; tile < 32; tile++) {
        int st = tile & 1;
        cp_wait<0>();
        __syncthreads();
        if (tile + 1 < 32) {
            long kb = ((long)bh * SEQ + (tile + 1) * 64) * HD;
            uint32_t kdst = sbase + AT_K + (st ^ 1) * AT_KB;
            uint32_t vdst = sbase + AT_V + (st ^ 1) * AT_KB;
            #pragma unroll
            for (int r = 0; r < 4; r++) {
                int u = tid + r * 128;
                int row = u >> 3, q = u & 7;
                uint32_t so = (uint32_t)(row * AT_LD + q * 8) * 2;
                cp_async16(kdst + so, &g_kb[kb + (long)row * HD + q * 8]);
                cp_async16(vdst + so, &g_vb[kb + (long)row * HD + q * 8]);
            }
            CP_COMMIT();
        }

        uint32_t Kst = sbase + AT_K + st * AT_KB;
        uint32_t Vst = sbase + AT_V + st * AT_KB;

        float sc[2][8][4];
        #pragma unroll
        for (int kg = 0; kg < 8; kg++) {
            uint32_t kaddr = Kst + (uint32_t)((kg * 8 + (lane & 7)) * AT_LD + (lane >> 3) * 8) * 2;
            uint32_t kb0[4], kb1[4];
            ldsm_x4(kb0, kaddr);
            ldsm_x4(kb1, kaddr + 64);
            #pragma unroll
            for (int mg = 0; mg < 2; mg++) {
                #pragma unroll
                for (int j = 0; j < 4; j++) sc[mg][kg][j] = 0.f;
                mma16816(sc[mg][kg], qa[mg][0], kb0[0], kb0[1]);
                mma16816(sc[mg][kg], qa[mg][1], kb0[2], kb0[3]);
                mma16816(sc[mg][kg], qa[mg][2], kb1[0], kb1[1]);
                mma16816(sc[mg][kg], qa[mg][3], kb1[2], kb1[3]);
            }
        }

        uint32_t pa[2][4][4];
        #pragma unroll
        for (int mg = 0; mg < 2; mg++) {
            #pragma unroll
            for (int kp = 0; kp < 4; kp++) {
                float e0 = __expf(sc[mg][2*kp][0]),   e1 = __expf(sc[mg][2*kp][1]);
                float e2 = __expf(sc[mg][2*kp][2]),   e3 = __expf(sc[mg][2*kp][3]);
                float f0 = __expf(sc[mg][2*kp+1][0]), f1 = __expf(sc[mg][2*kp+1][1]);
                float f2 = __expf(sc[mg][2*kp+1][2]), f3 = __expf(sc[mg][2*kp+1][3]);
                rs[mg][0] += (e0 + e1) + (f0 + f1);
                rs[mg][1] += (e2 + e3) + (f2 + f3);
                pa[mg][kp][0] = h2pack(e0, e1);
                pa[mg][kp][1] = h2pack(e2, e3);
                pa[mg][kp][2] = h2pack(f0, f1);
                pa[mg][kp][3] = h2pack(f2, f3);
            }
        }

        #pragma unroll
        for (int kp = 0; kp < 4; kp++) {
            #pragma unroll
            for (int np = 0; np < 4; np++) {
                uint32_t vaddr = Vst + (uint32_t)((kp * 16 + (lane & 15)) * AT_LD
                                                  + np * 16 + (lane >> 4) * 8) * 2;
                uint32_t vb[4];
                ldsm_x4_t(vb, vaddr);
                #pragma unroll
                for (int mg = 0; mg < 2; mg++) {
                    mma16816(oc[mg][np * 2],     pa[mg][kp], vb[0], vb[1]);
                    mma16816(oc[mg][np * 2 + 1], pa[mg][kp], vb[2], vb[3]);
                }
            }
        }
    }

    #pragma unroll
    for (int mg = 0; mg < 2; mg++) {
        rs[mg][0] += __shfl_xor_sync(0xffffffffu, rs[mg][0], 1);
        rs[mg][0] += __shfl_xor_sync(0xffffffffu, rs[mg][0], 2);
        rs[mg][1] += __shfl_xor_sync(0xffffffffu, rs[mg][1], 1);
        rs[mg][1] += __shfl_xor_sync(0xffffffffu, rs[mg][1], 2);
    }

    int b = bh >> 4, h = bh & 15;
    #pragma unroll
    for (int mg = 0; mg < 2; mg++) {
        float inv0 = 1.f / rs[mg][0], inv1 = 1.f / rs[mg][1];
        int r0 = q0 + warp * 32 + mg * 16 + (lane >> 2);
        long ob0 = (long)(b * SEQ + r0) * CDIM + h * HD;
        long ob1 = ob0 + 8L * CDIM;
        #pragma unroll
        for (int dg = 0; dg < 8; dg++) {
            int col = dg * 8 + (lane & 3) * 2;
            *(uint32_t*)&g_ao[ob0 + col] = h2pack(oc[mg][dg][0] * inv0, oc[mg][dg][1] * inv0);
            *(uint32_t*)&g_ao[ob1 + col] = h2pack(oc[mg][dg][2] * inv1, oc[mg][dg][3] * inv1);
        }
    }
}

// ---------------------------------------------------------------------------
// Host: tensormap construction via driver entry point (no -lcuda needed)
// ---------------------------------------------------------------------------
typedef CUresult (*EncodeTiledFn)(
    CUtensorMap*, CUtensorMapDataType, cuuint32_t, void*,
    const cuuint64_t*, const cuuint64_t*, const cuuint32_t*, const cuuint32_t*,
    CUtensorMapInterleave, CUtensorMapSwizzle, CUtensorMapL2promotion,
    CUtensorMapFloatOOBfill);

static void make_map(EncodeTiledFn enc, CUtensorMap* tm, void* ptr, uint64_t rows) {
    cuuint64_t dims[2]    = {(cuuint64_t)CDIM, (cuuint64_t)rows};
    cuuint64_t strides[1] = {(cuuint64_t)CDIM * 2};
    cuuint32_t box[2]     = {64, 128};
    cuuint32_t estr[2]    = {1, 1};
    enc(tm, CU_TENSOR_MAP_DATA_TYPE_FLOAT16, 2, ptr, dims, strides, box, estr,
        CU_TENSOR_MAP_INTERLEAVE_NONE, CU_TENSOR_MAP_SWIZZLE_128B,
        CU_TENSOR_MAP_L2_PROMOTION_L2_128B, CU_TENSOR_MAP_FLOAT_OOB_FILL_NONE);
}

extern "C" void kernel_launch(void* const* d_in, const int* in_sizes, int n_in,
                              void* d_out, int out_size) {
    const float* x     = (const float*)d_in[0];
    const float* qkv_w = (const float*)d_in[1];
    const float* qkv_b = (const float*)d_in[2];
    const float* fc_w  = (const float*)d_in[3];
    const float* fc_b  = (const float*)d_in[4];
    float* out = (float*)d_out;

    static bool init_done = false;
    static CUtensorMap tmX, tmW, tmF, tmAO;
    if (!init_done) {
        cudaFuncSetAttribute(gemm_qkv_tma, cudaFuncAttributeMaxDynamicSharedMemorySize, GT_SMEM);
        cudaFuncSetAttribute(gemm_out_tma, cudaFuncAttributeMaxDynamicSharedMemorySize, GT_SMEM);
        cudaFuncSetAttribute(attn_mma,     cudaFuncAttributeMaxDynamicSharedMemorySize, AT_SMEM);
        EncodeTiledFn enc = nullptr;
        cudaDriverEntryPointQueryResult qst;
        cudaGetDriverEntryPoint("cuTensorMapEncodeTiled", (void**)&enc,
                                cudaEnableDefault, &qst);
        void *px, *pw, *pf, *pao;
        cudaGetSymbolAddress(&px,  g_xh);
        cudaGetSymbolAddress(&pw,  g_wh);
        cudaGetSymbolAddress(&pf,  g_fh);
        cudaGetSymbolAddress(&pao, g_ao);
        make_map(enc, &tmX,  px,  MTOT);
        make_map(enc, &tmW,  pw,  N3);
        make_map(enc, &tmF,  pf,  CDIM);
        make_map(enc, &tmAO, pao, MTOT);
        init_done = true;
    }

    cvt_all_kernel<<<(CVT_NX + CVT_NW + CVT_NF) / 256, 256>>>(x, qkv_w, fc_w);

    dim3 g1(N3 / 128, MTOT / 128);     // 24 x 64
    gemm_qkv_tma<<<g1, 128, GT_SMEM>>>(tmX, tmW, qkv_b);

    dim3 ga(SEQ / 128, BATCH * NH);    // 16 x 64
    attn_mma<<<ga, 128, AT_SMEM>>>();

    dim3 g2(CDIM / 128, MTOT / 128);   // 8 x 64
    gemm_out_tma<<<g2, 128, GT_SMEM>>>(tmAO, tmF, fc_b, out);
}

// round 16
// speedup vs baseline: 1.2748x; 1.0214x over previous
#include <cuda_runtime.h>
#include <cuda.h>
#include <cuda_fp16.h>
#include <cstdint>

#define BATCH 4
#define SEQ   2048
#define CDIM  1024
#define NH    16
#define HD    64
#define MTOT  (BATCH*SEQ)   // 8192
#define N3    (3*CDIM)      // 3072

// ---------------- scratch (device globals; no allocation) ----------------
__device__ __half g_xh[MTOT*CDIM];                     // x (fp16)
__device__ __half g_wh[N3*CDIM];                       // qkv_w (fp16)
__device__ __half g_fh[CDIM*CDIM];                     // fc_w (fp16)
__device__ __half g_qb[BATCH*NH*SEQ*HD];               // Q (pre-scaled by 0.125)
__device__ __half g_kb[BATCH*NH*SEQ*HD];               // K
__device__ __half g_vb[BATCH*NH*SEQ*HD];               // V [bh][t][d]
__device__ __half g_ao[MTOT*CDIM];                     // attn out (fp16)

// ---------------- helpers ----------------
__device__ __forceinline__ uint32_t smem_u32(const void* p) {
    uint32_t a;
    asm("{ .reg .u64 t; cvta.to.shared.u64 t, %1; cvt.u32.u64 %0, t; }" : "=r"(a) : "l"(p));
    return a;
}
__device__ __forceinline__ void ldsm_x4(uint32_t* r, uint32_t addr) {
    asm volatile("ldmatrix.sync.aligned.m8n8.x4.shared.b16 {%0,%1,%2,%3}, [%4];"
        : "=r"(r[0]), "=r"(r[1]), "=r"(r[2]), "=r"(r[3]) : "r"(addr));
}
__device__ __forceinline__ void ldsm_x4_t(uint32_t* r, uint32_t addr) {
    asm volatile("ldmatrix.sync.aligned.m8n8.x4.trans.shared.b16 {%0,%1,%2,%3}, [%4];"
        : "=r"(r[0]), "=r"(r[1]), "=r"(r[2]), "=r"(r[3]) : "r"(addr));
}
__device__ __forceinline__ void mma16816(float* c, const uint32_t* a, uint32_t b0, uint32_t b1) {
    asm volatile("mma.sync.aligned.m16n8k16.row.col.f32.f16.f16.f32 "
        "{%0,%1,%2,%3}, {%4,%5,%6,%7}, {%8,%9}, {%0,%1,%2,%3};"
        : "+f"(c[0]), "+f"(c[1]), "+f"(c[2]), "+f"(c[3])
        : "r"(a[0]), "r"(a[1]), "r"(a[2]), "r"(a[3]), "r"(b0), "r"(b1));
}
__device__ __forceinline__ uint32_t h2pack(float a, float b) {
    __half2 p = __floats2half2_rn(a, b);
    return *(uint32_t*)&p;
}
// mbarrier
#define MBARRIER_INIT(mb, c) \
    asm volatile("mbarrier.init.shared.b64 [%0], %1;" :: "r"((uint32_t)(mb)), "r"((uint32_t)(c)) : "memory")
#define MBARRIER_EXPECT_TX(mb, tx) \
    asm volatile("mbarrier.arrive.expect_tx.shared.b64 _, [%0], %1;" \
                 :: "r"((uint32_t)(mb)), "r"((uint32_t)(tx)) : "memory")
#define MBARRIER_WAIT_PARITY(mb, ph) do { \
    uint32_t _m = (uint32_t)(mb), _p = (uint32_t)(ph), _d; \
    asm volatile("{\n\t.reg .pred p;\n\t" \
        "mbarrier.try_wait.parity.acquire.cta.shared::cta.b64 p, [%1], %2;\n\t" \
        "selp.b32 %0, 1, 0, p;\n\t}" : "=r"(_d) : "r"(_m), "r"(_p) : "memory"); \
    if (!_d) { \
        asm volatile("{\n\t.reg .pred P1;\n\t" \
            "WL_%=:\n\t" \
            "mbarrier.try_wait.parity.acquire.cta.shared::cta.b64 P1, [%0], %1, 0x989680;\n\t" \
            "@P1 bra.uni WD_%=;\n\tbra.uni WL_%=;\n\tWD_%=:\n\t}" \
            :: "r"(_m), "r"(_p) : "memory"); \
    } \
} while(0)
// 2D TMA load: global -> shared::cta, mbarrier complete_tx
__device__ __forceinline__ void tma2d(uint32_t dst, const CUtensorMap* m,
                                      int x, int y, uint32_t mbar) {
    asm volatile(
        "cp.async.bulk.tensor.2d.shared::cta.global.tile.mbarrier::complete_tx::bytes "
        "[%0], [%1, {%2, %3}], [%4];"
        :: "r"(dst), "l"(m), "r"(x), "r"(y), "r"(mbar) : "memory");
}
#define GSWZ(o) ((o) ^ (((o) >> 3) & 0x70))

// ---------------- fp32 -> fp16 conversion (single fused launch) ----------------
#define CVT_NX (MTOT * CDIM / 4)
#define CVT_NW (N3 * CDIM / 4)
#define CVT_NF (CDIM * CDIM / 4)
__global__ __launch_bounds__(256) void cvt_all_kernel(const float* __restrict__ x,
                                                      const float* __restrict__ w,
                                                      const float* __restrict__ f) {
    int i = blockIdx.x * blockDim.x + threadIdx.x;
    const float4* src;
    uint2* dst;
    int j;
    if (i < CVT_NX)                { src = (const float4*)x; dst = (uint2*)g_xh; j = i; }
    else if (i < CVT_NX + CVT_NW)  { src = (const float4*)w; dst = (uint2*)g_wh; j = i - CVT_NX; }
    else                           { src = (const float4*)f; dst = (uint2*)g_fh; j = i - CVT_NX - CVT_NW; }
    float4 v = src[j];
    dst[j] = make_uint2(h2pack(v.x, v.y), h2pack(v.z, v.w));
}

// ---------------------------------------------------------------------------
// GEMM (TMA + raw mma, unchanged from R15): block 128x128, 4 warps (2x2),
// warp tile 64x64, K-chunk 64, 3-stage, single barrier per chunk.
// ---------------------------------------------------------------------------
#define GT_STAGE 32768
#define GT_MBAR  (3 * GT_STAGE)          // 98304
#define GT_SMEM  (GT_MBAR + 128)
#define G_NCH    (CDIM / 64)             // 16

#define GEMM_TMA_ISSUE(ch, st) do { \
    if (tid == 0) { \
        uint32_t mb_ = sbase + GT_MBAR + (st) * 8; \
        MBARRIER_EXPECT_TX(mb_, (uint32_t)GT_STAGE); \
        tma2d(sbase + (st) * GT_STAGE,         &tmA, (ch) * 64, bm, mb_); \
        tma2d(sbase + (st) * GT_STAGE + 16384, &tmB, (ch) * 64, bn, mb_); \
    } \
} while (0)

#define GEMM_COMPUTE(st) do { \
    uint32_t Ast_ = sbase + (st) * GT_STAGE; \
    uint32_t Bst_ = Ast_ + 16384; \
    _Pragma("unroll") \
    for (int kb_ = 0; kb_ < 2; kb_++) { \
        uint32_t bb_[8][4]; \
        _Pragma("unroll") \
        for (int ng_ = 0; ng_ < 8; ng_++) { \
            uint32_t o_ = (uint32_t)((wn * 64 + ng_ * 8 + (lane & 7)) * 128 \
                                     + kb_ * 64 + (lane >> 3) * 16); \
            ldsm_x4(bb_[ng_], Bst_ + GSWZ(o_)); \
        } \
        _Pragma("unroll") \
        for (int ks_ = 0; ks_ < 2; ks_++) { \
            uint32_t a_[4][4]; \
            _Pragma("unroll") \
            for (int mi_ = 0; mi_ < 4; mi_++) { \
                uint32_t o_ = (uint32_t)((wm * 64 + mi_ * 16 + (lane & 15)) * 128 \
                                         + kb_ * 64 + ks_ * 32 + (lane >> 4) * 16); \
                ldsm_x4(a_[mi_], Ast_ + GSWZ(o_)); \
            } \
            _Pragma("unroll") \
            for (int mi_ = 0; mi_ < 4; mi_++) \
                _Pragma("unroll") \
                for (int ng_ = 0; ng_ < 8; ng_++) \
                    mma16816(acc[mi_][ng_], a_[mi_], bb_[ng_][ks_ * 2], bb_[ng_][ks_ * 2 + 1]); \
        } \
    } \
} while (0)

#define GEMM_MAINLOOP() do { \
    if (tid == 0) { \
        MBARRIER_INIT(sbase + GT_MBAR + 0, 1); \
        MBARRIER_INIT(sbase + GT_MBAR + 8, 1); \
        MBARRIER_INIT(sbase + GT_MBAR + 16, 1); \
    } \
    __syncthreads(); \
    GEMM_TMA_ISSUE(0, 0); \
    GEMM_TMA_ISSUE(1, 1); \
    for (int ch = 0; ch < G_NCH; ch++) { \
        int st = ch % 3; \
        MBARRIER_WAIT_PARITY(sbase + GT_MBAR + st * 8, (ch / 3) & 1); \
        __syncthreads(); \
        if (ch + 2 < G_NCH) GEMM_TMA_ISSUE(ch + 2, (ch + 2) % 3); \
        GEMM_COMPUTE(st); \
    } \
} while (0)

// ---------------- GEMM1: qkv = x @ qkv_w^T + b ; scatter q/k/v fp16 ----------------
__global__ __launch_bounds__(128, 2) void gemm_qkv_tma(
    const __grid_constant__ CUtensorMap tmA,
    const __grid_constant__ CUtensorMap tmB,
    const float* __restrict__ bias)
{
    extern __shared__ __align__(128) char smraw[];
    uint32_t sbase = smem_u32(smraw);
    int tid = threadIdx.x, warp = tid >> 5, lane = tid & 31;
    int wm = warp >> 1, wn = warp & 1;
    int bm = blockIdx.y * 128, bn = blockIdx.x * 128;

    float acc[4][8][4];
    #pragma unroll
    for (int i = 0; i < 4; i++)
        #pragma unroll
        for (int j = 0; j < 8; j++)
            #pragma unroll
            for (int c = 0; c < 4; c++) acc[i][j][c] = 0.f;

    GEMM_MAINLOOP();

    // epilogue: register -> GMEM scatter (no smem staging)
    int b = bm >> 11;
    int colp = (lane & 3) * 2;
    float bias0[8], bias1[8], scale[8];
    __half* base[8];
    #pragma unroll
    for (int ng = 0; ng < 8; ng++) {
        int n0 = bn + wn * 64 + ng * 8 + colp;
        bias0[ng] = __ldg(&bias[n0]);
        bias1[ng] = __ldg(&bias[n0 + 1]);
        int which = n0 >> 10;
        int rem = n0 & 1023;
        int h = rem >> 6, d0 = rem & 63;
        scale[ng] = (which == 0) ? 0.125f : 1.0f;
        base[ng] = (which == 0 ? g_qb : which == 1 ? g_kb : g_vb)
                 + ((long)(b * NH + h) * SEQ) * HD + d0;
    }
    #pragma unroll
    for (int mi = 0; mi < 4; mi++) {
        int m0 = bm + wm * 64 + mi * 16 + (lane >> 2);
        #pragma unroll
        for (int rr = 0; rr < 2; rr++) {
            int t = (m0 + rr * 8) & (SEQ - 1);
            #pragma unroll
            for (int ng = 0; ng < 8; ng++) {
                float v0 = (acc[mi][ng][rr * 2]     + bias0[ng]) * scale[ng];
                float v1 = (acc[mi][ng][rr * 2 + 1] + bias1[ng]) * scale[ng];
                *(uint32_t*)(base[ng] + (long)t * HD) = h2pack(v0, v1);
            }
        }
    }
}

// ---------------- GEMM2: out = ao @ fc_w^T + b (fp32 out) ----------------
__global__ __launch_bounds__(128, 2) void gemm_out_tma(
    const __grid_constant__ CUtensorMap tmA,
    const __grid_constant__ CUtensorMap tmB,
    const float* __restrict__ bias, float* __restrict__ out)
{
    extern __shared__ __align__(128) char smraw[];
    uint32_t sbase = smem_u32(smraw);
    int tid = threadIdx.x, warp = tid >> 5, lane = tid & 31;
    int wm = warp >> 1, wn = warp & 1;
    int bm = blockIdx.y * 128, bn = blockIdx.x * 128;

    float acc[4][8][4];
    #pragma unroll
    for (int i = 0; i < 4; i++)
        #pragma unroll
        for (int j = 0; j < 8; j++)
            #pragma unroll
            for (int c = 0; c < 4; c++) acc[i][j][c] = 0.f;

    GEMM_MAINLOOP();

    int colp = (lane & 3) * 2;
    float bias0[8], bias1[8];
    int ncol[8];
    #pragma unroll
    for (int ng = 0; ng < 8; ng++) {
        int n0 = bn + wn * 64 + ng * 8 + colp;
        ncol[ng] = n0;
        bias0[ng] = __ldg(&bias[n0]);
        bias1[ng] = __ldg(&bias[n0 + 1]);
    }
    #pragma unroll
    for (int mi = 0; mi < 4; mi++) {
        int m0 = bm + wm * 64 + mi * 16 + (lane >> 2);
        #pragma unroll
        for (int rr = 0; rr < 2; rr++) {
            long mrow = (long)(m0 + rr * 8) * CDIM;
            #pragma unroll
            for (int ng = 0; ng < 8; ng++) {
                float2 v;
                v.x = acc[mi][ng][rr * 2]     + bias0[ng];
                v.y = acc[mi][ng][rr * 2 + 1] + bias1[ng];
                *(float2*)(out + mrow + ncol[ng]) = v;
            }
        }
    }
}

// ---------------------------------------------------------------------------
// Attention: FA2-style raw mma + TMA K/V loads. Block = 128 queries, 128 thr
// (4 warps x 2 m-groups). 64-key tiles (128 B rows, SW128), 2-stage mbarrier.
// smem: Qs[128][72]h pad | K 2x[64x128B] swz | V 2x[64x128B] swz | mbars
// ---------------------------------------------------------------------------
#define AT_LD   72
#define AT_QB   (128 * AT_LD * 2)            // 18432
#define AT_KB   8192                          // one swizzled K or V stage
#define AT_Q    0
#define AT_K    (AT_QB)                       // stages: +0, +AT_KB
#define AT_V    (AT_QB + 2 * AT_KB)           // stages: +0, +AT_KB
#define AT_MBAR (AT_QB + 4 * AT_KB)           // 2 mbarriers
#define AT_SMEM (AT_MBAR + 128)               // 51328

#define ATT_ISSUE(tile_, st_) do { \
    if (tid == 0) { \
        uint32_t mb_ = sbase + AT_MBAR + (st_) * 8; \
        MBARRIER_EXPECT_TX(mb_, 2u * AT_KB); \
        int y_ = bh * SEQ + (tile_) * 64; \
        tma2d(sbase + AT_K + (st_) * AT_KB, &tmK, 0, y_, mb_); \
        tma2d(sbase + AT_V + (st_) * AT_KB, &tmV, 0, y_, mb_); \
    } \
} while (0)

__global__ __launch_bounds__(128, 2) void attn_mma(
    const __grid_constant__ CUtensorMap tmK,
    const __grid_constant__ CUtensorMap tmV)
{
    extern __shared__ __align__(128) char smraw[];
    uint32_t sbase = smem_u32(smraw);
    __half* Qs = (__half*)(smraw + AT_Q);

    int tid = threadIdx.x, warp = tid >> 5, lane = tid & 31;
    int bh = blockIdx.y;
    int q0 = blockIdx.x * 128;
    long qbase = ((long)bh * SEQ + q0) * HD;

    if (tid == 0) {
        MBARRIER_INIT(sbase + AT_MBAR + 0, 1);
        MBARRIER_INIT(sbase + AT_MBAR + 8, 1);
    }
    __syncthreads();
    ATT_ISSUE(0, 0);

    // load Q (128 rows) to padded smem
    #pragma unroll
    for (int r = 0; r < 8; r++) {
        int u = tid + r * 128;
        int row = u >> 3, q = u & 7;
        *(uint4*)&Qs[row * AT_LD + q * 8] =
            *(const uint4*)&g_qb[qbase + (long)row * HD + q * 8];
    }
    __syncthreads();

    // Q fragments: 2 m-groups x 4 ksteps
    uint32_t qa[2][4][4];
    #pragma unroll
    for (int mg = 0; mg < 2; mg++) {
        uint32_t qrow = warp * 32 + mg * 16 + (lane & 15);
        #pragma unroll
        for (int kk = 0; kk < 4; kk++) {
            uint32_t addr = sbase + AT_Q + (uint32_t)(qrow * AT_LD + kk * 16 + (lane >> 4) * 8) * 2;
            ldsm_x4(qa[mg][kk], addr);
        }
    }

    float oc[2][8][4];
    #pragma unroll
    for (int mg = 0; mg < 2; mg++)
        #pragma unroll
        for (int i = 0; i < 8; i++)
            #pragma unroll
            for (int j = 0; j < 4; j++) oc[mg][i][j] = 0.f;
    float rs[2][2] = {{0.f, 0.f}, {0.f, 0.f}};

    for (int tile = 0; tile < 32; tile++) {
        int st = tile & 1;
        MBARRIER_WAIT_PARITY(sbase + AT_MBAR + st * 8, (tile >> 1) & 1);
        __syncthreads();
        if (tile + 1 < 32) ATT_ISSUE(tile + 1, st ^ 1);

        uint32_t Kst = sbase + AT_K + st * AT_KB;
        uint32_t Vst = sbase + AT_V + st * AT_KB;

        // S = Q K^T for both m-groups; K fragments shared across mg
        float sc[2][8][4];
        #pragma unroll
        for (int kg = 0; kg < 8; kg++) {
            uint32_t o0 = (uint32_t)((kg * 8 + (lane & 7)) * 128 + (lane >> 3) * 16);
            uint32_t kb0[4], kb1[4];
            ldsm_x4(kb0, Kst + GSWZ(o0));         // dims 0-31
            ldsm_x4(kb1, Kst + GSWZ(o0 + 64));    // dims 32-63
            #pragma unroll
            for (int mg = 0; mg < 2; mg++) {
                #pragma unroll
                for (int j = 0; j < 4; j++) sc[mg][kg][j] = 0.f;
                mma16816(sc[mg][kg], qa[mg][0], kb0[0], kb0[1]);
                mma16816(sc[mg][kg], qa[mg][1], kb0[2], kb0[3]);
                mma16816(sc[mg][kg], qa[mg][2], kb1[0], kb1[1]);
                mma16816(sc[mg][kg], qa[mg][3], kb1[2], kb1[3]);
            }
        }

        // exp in registers; build P A-fragments
        uint32_t pa[2][4][4];
        #pragma unroll
        for (int mg = 0; mg < 2; mg++) {
            #pragma unroll
            for (int kp = 0; kp < 4; kp++) {
                float e0 = __expf(sc[mg][2*kp][0]),   e1 = __expf(sc[mg][2*kp][1]);
                float e2 = __expf(sc[mg][2*kp][2]),   e3 = __expf(sc[mg][2*kp][3]);
                float f0 = __expf(sc[mg][2*kp+1][0]), f1 = __expf(sc[mg][2*kp+1][1]);
                float f2 = __expf(sc[mg][2*kp+1][2]), f3 = __expf(sc[mg][2*kp+1][3]);
                rs[mg][0] += (e0 + e1) + (f0 + f1);
                rs[mg][1] += (e2 + e3) + (f2 + f3);
                pa[mg][kp][0] = h2pack(e0, e1);
                pa[mg][kp][1] = h2pack(e2, e3);
                pa[mg][kp][2] = h2pack(f0, f1);
                pa[mg][kp][3] = h2pack(f2, f3);
            }
        }

        // O += P V; V fragments shared across mg
        #pragma unroll
        for (int kp = 0; kp < 4; kp++) {
            #pragma unroll
            for (int np = 0; np < 4; np++) {
                uint32_t o0 = (uint32_t)((kp * 16 + (lane & 15)) * 128
                                         + np * 32 + (lane >> 4) * 16);
                uint32_t vb[4];
                ldsm_x4_t(vb, Vst + GSWZ(o0));
                #pragma unroll
                for (int mg = 0; mg < 2; mg++) {
                    mma16816(oc[mg][np * 2],     pa[mg][kp], vb[0], vb[1]);
                    mma16816(oc[mg][np * 2 + 1], pa[mg][kp], vb[2], vb[3]);
                }
            }
        }
    }

    // row-sum reduction within quads
    #pragma unroll
    for (int mg = 0; mg < 2; mg++) {
        rs[mg][0] += __shfl_xor_sync(0xffffffffu, rs[mg][0], 1);
        rs[mg][0] += __shfl_xor_sync(0xffffffffu, rs[mg][0], 2);
        rs[mg][1] += __shfl_xor_sync(0xffffffffu, rs[mg][1], 1);
        rs[mg][1] += __shfl_xor_sync(0xffffffffu, rs[mg][1], 2);
    }

    // write O (fp16) to g_ao
    int b = bh >> 4, h = bh & 15;
    #pragma unroll
    for (int mg = 0; mg < 2; mg++) {
        float inv0 = 1.f / rs[mg][0], inv1 = 1.f / rs[mg][1];
        int r0 = q0 + warp * 32 + mg * 16 + (lane >> 2);
        long ob0 = (long)(b * SEQ + r0) * CDIM + h * HD;
        long ob1 = ob0 + 8L * CDIM;
        #pragma unroll
        for (int dg = 0; dg < 8; dg++) {
            int col = dg * 8 + (lane & 3) * 2;
            *(uint32_t*)&g_ao[ob0 + col] = h2pack(oc[mg][dg][0] * inv0, oc[mg][dg][1] * inv0);
            *(uint32_t*)&g_ao[ob1 + col] = h2pack(oc[mg][dg][2] * inv1, oc[mg][dg][3] * inv1);
        }
    }
}

// ---------------------------------------------------------------------------
// Host: tensormap construction via driver entry point (no -lcuda needed)
// ---------------------------------------------------------------------------
typedef CUresult (*EncodeTiledFn)(
    CUtensorMap*, CUtensorMapDataType, cuuint32_t, void*,
    const cuuint64_t*, const cuuint64_t*, const cuuint32_t*, const cuuint32_t*,
    CUtensorMapInterleave, CUtensorMapSwizzle, CUtensorMapL2promotion,
    CUtensorMapFloatOOBfill);

static void make_map(EncodeTiledFn enc, CUtensorMap* tm, void* ptr, uint64_t rows) {
    cuuint64_t dims[2]    = {(cuuint64_t)CDIM, (cuuint64_t)rows};
    cuuint64_t strides[1] = {(cuuint64_t)CDIM * 2};
    cuuint32_t box[2]     = {64, 128};
    cuuint32_t estr[2]    = {1, 1};
    enc(tm, CU_TENSOR_MAP_DATA_TYPE_FLOAT16, 2, ptr, dims, strides, box, estr,
        CU_TENSOR_MAP_INTERLEAVE_NONE, CU_TENSOR_MAP_SWIZZLE_128B,
        CU_TENSOR_MAP_L2_PROMOTION_L2_128B, CU_TENSOR_MAP_FLOAT_OOB_FILL_NONE);
}
static void make_map_kv(EncodeTiledFn enc, CUtensorMap* tm, void* ptr) {
    cuuint64_t dims[2]    = {(cuuint64_t)HD, (cuuint64_t)BATCH * NH * SEQ};
    cuuint64_t strides[1] = {(cuuint64_t)HD * 2};
    cuuint32_t box[2]     = {64, 64};
    cuuint32_t estr[2]    = {1, 1};
    enc(tm, CU_TENSOR_MAP_DATA_TYPE_FLOAT16, 2, ptr, dims, strides, box, estr,
        CU_TENSOR_MAP_INTERLEAVE_NONE, CU_TENSOR_MAP_SWIZZLE_128B,
        CU_TENSOR_MAP_L2_PROMOTION_L2_128B, CU_TENSOR_MAP_FLOAT_OOB_FILL_NONE);
}

extern "C" void kernel_launch(void* const* d_in, const int* in_sizes, int n_in,
                              void* d_out, int out_size) {
    const float* x     = (const float*)d_in[0];
    const float* qkv_w = (const float*)d_in[1];
    const float* qkv_b = (const float*)d_in[2];
    const float* fc_w  = (const float*)d_in[3];
    const float* fc_b  = (const float*)d_in[4];
    float* out = (float*)d_out;

    static bool init_done = false;
    static CUtensorMap tmX, tmW, tmF, tmAO, tmK, tmV;
    if (!init_done) {
        cudaFuncSetAttribute(gemm_qkv_tma, cudaFuncAttributeMaxDynamicSharedMemorySize, GT_SMEM);
        cudaFuncSetAttribute(gemm_out_tma, cudaFuncAttributeMaxDynamicSharedMemorySize, GT_SMEM);
        cudaFuncSetAttribute(attn_mma,     cudaFuncAttributeMaxDynamicSharedMemorySize, AT_SMEM);
        EncodeTiledFn enc = nullptr;
        cudaDriverEntryPointQueryResult qst;
        cudaGetDriverEntryPoint("cuTensorMapEncodeTiled", (void**)&enc,
                                cudaEnableDefault, &qst);
        void *px, *pw, *pf, *pao, *pk, *pv;
        cudaGetSymbolAddress(&px,  g_xh);
        cudaGetSymbolAddress(&pw,  g_wh);
        cudaGetSymbolAddress(&pf,  g_fh);
        cudaGetSymbolAddress(&pao, g_ao);
        cudaGetSymbolAddress(&pk,  g_kb);
        cudaGetSymbolAddress(&pv,  g_vb);
        make_map(enc, &tmX,  px,  MTOT);
        make_map(enc, &tmW,  pw,  N3);
        make_map(enc, &tmF,  pf,  CDIM);
        make_map(enc, &tmAO, pao, MTOT);
        make_map_kv(enc, &tmK, pk);
        make_map_kv(enc, &tmV, pv);
        init_done = true;
    }

    cvt_all_kernel<<<(CVT_NX + CVT_NW + CVT_NF) / 256, 256>>>(x, qkv_w, fc_w);

    dim3 g1(N3 / 128, MTOT / 128);     // 24 x 64
    gemm_qkv_tma<<<g1, 128, GT_SMEM>>>(tmX, tmW, qkv_b);

    dim3 ga(SEQ / 128, BATCH * NH);    // 16 x 64
    attn_mma<<<ga, 128, AT_SMEM>>>(tmK, tmV);

    dim3 g2(CDIM / 128, MTOT / 128);   // 8 x 64
    gemm_out_tma<<<g2, 128, GT_SMEM>>>(tmAO, tmF, fc_b, out);
}